// round 13
// baseline (speedup 1.0000x reference)
#include <cuda_runtime.h>
#include <cuda_fp16.h>
#include <math.h>
#include <stdint.h>

// Problem constants
#define BB 2
#define SS 2048
#define DD 1024
#define HH 16
#define DQ 64

// Attention tiling
#define BM 64

// ctx scratch (single fp16)
__device__ __half g_ctx_h[BB * SS * DD];
// W hi fp16
__device__ __half g_w_h[DD * DD];
// K hi; V hi (single fp16 each)
__device__ __half g_k_h[BB * SS * DD];
__device__ __half g_v_h[BB * SS * DD];

// ===========================================================================
// Helpers
// ===========================================================================
__device__ __forceinline__ uint32_t smem_u32(const void* p) {
    uint32_t a;
    asm("{ .reg .u64 t; cvta.to.shared.u64 t, %1; cvt.u32.u64 %0, t; }" : "=r"(a) : "l"(p));
    return a;
}
__device__ __forceinline__ uint32_t swz(uint32_t off) {
    return off ^ ((off >> 3) & 0x70);
}
__device__ __forceinline__ void ldsm4(uint32_t* r, uint32_t addr) {
    asm volatile("ldmatrix.sync.aligned.m8n8.x4.shared.b16 {%0,%1,%2,%3}, [%4];"
                 : "=r"(r[0]), "=r"(r[1]), "=r"(r[2]), "=r"(r[3]) : "r"(addr));
}
__device__ __forceinline__ void ldsm4t(uint32_t* r, uint32_t addr) {
    asm volatile("ldmatrix.sync.aligned.m8n8.x4.trans.shared.b16 {%0,%1,%2,%3}, [%4];"
                 : "=r"(r[0]), "=r"(r[1]), "=r"(r[2]), "=r"(r[3]) : "r"(addr));
}
__device__ __forceinline__ void mma16816(float* c, const uint32_t* a, uint32_t b0, uint32_t b1) {
    asm volatile("mma.sync.aligned.m16n8k16.row.col.f32.f16.f16.f32 "
                 "{%0,%1,%2,%3}, {%4,%5,%6,%7}, {%8,%9}, {%0,%1,%2,%3};"
                 : "+f"(c[0]), "+f"(c[1]), "+f"(c[2]), "+f"(c[3])
                 : "r"(a[0]), "r"(a[1]), "r"(a[2]), "r"(a[3]), "r"(b0), "r"(b1));
}
__device__ __forceinline__ uint2 pack4h(float4 v) {
    __half2 a = __floats2half2_rn(v.x, v.y);
    __half2 b = __floats2half2_rn(v.z, v.w);
    uint2 r;
    r.x = *reinterpret_cast<uint32_t*>(&a);
    r.y = *reinterpret_cast<uint32_t*>(&b);
    return r;
}
__device__ __forceinline__ uint32_t pack2h(float x, float y) {
    __half2 h = __floats2half2_rn(x, y);
    return *reinterpret_cast<uint32_t*>(&h);
}
__device__ __forceinline__ void cpa16(uint32_t d, const void* s) {
    asm volatile("cp.async.cg.shared.global [%0], [%1], 16;" :: "r"(d), "l"(s));
}
#define CP_COMMIT() asm volatile("cp.async.commit_group;" ::: "memory")
#define CP_WAIT0()  asm volatile("cp.async.wait_group 0;" ::: "memory")
#define CP_WAIT1()  asm volatile("cp.async.wait_group 1;" ::: "memory")

// ===========================================================================
// Fused converter: blocks [0,512) K-hi, [512,1024) V-hi, [1024,1152) W-hi.
// 8 float4 per thread; stores widened to uint4 (2 float4 -> 8 halves).
// ===========================================================================
extern "C" __global__ void __launch_bounds__(256)
convert_all(const float* __restrict__ K,
            const float* __restrict__ V,
            const float* __restrict__ W)
{
    const int bid = blockIdx.x;
    const int tid = threadIdx.x;
    float4 v[8];
    if (bid < 512) {
        int i0 = (bid * 256 + tid) * 8;
#pragma unroll
        for (int j = 0; j < 8; j++) v[j] = reinterpret_cast<const float4*>(K)[i0 + j];
#pragma unroll
        for (int j = 0; j < 4; j++) {
            uint2 a = pack4h(v[2 * j]), b = pack4h(v[2 * j + 1]);
            reinterpret_cast<uint4*>(g_k_h)[i0 / 2 + j] = make_uint4(a.x, a.y, b.x, b.y);
        }
    } else if (bid < 1024) {
        int i0 = ((bid - 512) * 256 + tid) * 8;
#pragma unroll
        for (int j = 0; j < 8; j++) v[j] = reinterpret_cast<const float4*>(V)[i0 + j];
#pragma unroll
        for (int j = 0; j < 4; j++) {
            uint2 a = pack4h(v[2 * j]), b = pack4h(v[2 * j + 1]);
            reinterpret_cast<uint4*>(g_v_h)[i0 / 2 + j] = make_uint4(a.x, a.y, b.x, b.y);
        }
    } else {
        int i0 = ((bid - 1024) * 256 + tid) * 8;
#pragma unroll
        for (int j = 0; j < 8; j++) v[j] = reinterpret_cast<const float4*>(W)[i0 + j];
#pragma unroll
        for (int j = 0; j < 4; j++) {
            uint2 a = pack4h(v[2 * j]), b = pack4h(v[2 * j + 1]);
            reinterpret_cast<uint4*>(g_w_h)[i0 / 2 + j] = make_uint4(a.x, a.y, b.x, b.y);
        }
    }
}

// ===========================================================================
// Row-0 fix: ctx(q=0) = mean_s V (fully-masked row -> uniform softmax)
// ===========================================================================
extern "C" __global__ void __launch_bounds__(256)
meanv_fix(const float* __restrict__ V)
{
    __shared__ float red[256];
    const int h = blockIdx.x, b = blockIdx.y;
    const int t = threadIdx.x;
    const int d = t & 63;
    const int sc = t >> 6;
    const float* src = V + (size_t)b * SS * DD + h * DQ + d;
    float s = 0.0f;
#pragma unroll 8
    for (int i = sc * 512; i < sc * 512 + 512; i++)
        s += src[(size_t)i * DD];
    red[t] = s;
    __syncthreads();
    if (t < 64) {
        float m = (red[t] + red[t + 64] + red[t + 128] + red[t + 192]) * (1.0f / 2048.0f);
        g_ctx_h[(size_t)b * SS * DD + h * DQ + d] = __float2half_rn(m);
    }
}

// ===========================================================================
// Attention smem: Q hi (8 KB) + 2 stages x (K 16KB + V 16KB) = 72 KB.
// Cross-warp reduce buffer reuses [0, ~18 KB) after the main loop.
// ===========================================================================
#define SM_QH   0
#define SM_STG  8192
#define STG_STR 32768
#define SMEM_BYTES 73728
#define RED_STR 35

// ===========================================================================
// Flash attention: fp16 HMMA, 128-key iterations (2 sub-tiles per sync),
// SINGLE __syncthreads per iteration, pipelined K/V. 8 warps (16 q-rows x
// 32 keys per sub-tile). QK 1-term, PV 1-term. Grid (32,16,2), 256 threads.
// ===========================================================================
extern "C" __global__ void __launch_bounds__(256, 2)
attn_mma(const float* __restrict__ Q)
{
    extern __shared__ char smc[];
    const uint32_t sb = smem_u32(smc);
    const int tid  = threadIdx.x;
    const int lane = tid & 31;
    const int wid  = tid >> 5;
    const int wr   = wid >> 1;    // row group 0..3
    const int wk   = wid & 1;     // key half (within 64-key sub-tile)

    const int bx = blockIdx.x;
    const int qt = (bx == 31) ? 0 : (31 - bx);
    const int h  = blockIdx.y;
    const int b  = blockIdx.z;
    const int q0 = qt * BM;

    const float* Qb  = Q + ((size_t)(b * SS + q0)) * DD + h * DQ;
    const size_t kvb = (size_t)b * SS * DD + h * DQ;

    const int nkt = qt + 1;            // 64-key sub-tiles
    const int nit = (nkt + 1) >> 1;    // 128-key iterations

    // Prefetch one 128-key stage: K 16 KB + V 16 KB. 8 chunks/thread.
    auto prefetch = [&](int stage, int k0) {
        const uint32_t stg = sb + SM_STG + stage * STG_STR;
#pragma unroll
        for (int q = 0; q < 4; q++) {
            const int id = q * 256 + tid;       // 0..1023
            const int r = id >> 3;              // row 0..127
            const int g = id & 7;
            int rr = k0 + r;
            if (rr > SS - 1) rr = SS - 1;       // clamp (tail rows fully masked)
            const uint32_t off = swz((uint32_t)(r * 128 + g * 16));
            const size_t srco = kvb + (size_t)rr * DD + g * 8;
            cpa16(stg + off,         &g_k_h[srco]);
            cpa16(stg + 16384 + off, &g_v_h[srco]);
        }
    };

    prefetch(0, 0);
    CP_COMMIT();

    // ---- Load Q tile (hi only; overlaps stage-0 prefetch) ----
#pragma unroll
    for (int it = 0; it < 4; it++) {
        int idx = it * 256 + tid;
        int r = idx >> 4;
        int g = idx & 15;
        float4 q4 = *reinterpret_cast<const float4*>(Qb + (size_t)r * DD + g * 4);
        uint32_t off = swz((uint32_t)(r * 128 + g * 8));
        *reinterpret_cast<uint2*>(smc + SM_QH + off) = pack4h(q4);
    }
    __syncthreads();

    // ---- Hoist Q fragments (loop-invariant) ----
    uint32_t ah[4][4];
#pragma unroll
    for (int kc = 0; kc < 4; kc++) {
        uint32_t offA = swz((uint32_t)((wr * 16 + (lane & 15)) * 128 +
                                       (kc * 16 + (lane >> 4) * 8) * 2));
        ldsm4(ah[kc], sb + SM_QH + offA);
    }

    float Oa[32];
    float l0 = 0.0f, l1 = 0.0f;
#pragma unroll
    for (int i = 0; i < 32; i++) Oa[i] = 0.0f;

    const int qg0 = q0 + wr * 16 + (lane >> 2);
    const int qg1 = qg0 + 8;

    for (int it = 0; it < nit; it++) {
        const int k0 = it * 128;

        CP_WAIT0();          // stage (it&1) data landed (this thread's chunks)
        __syncthreads();     // all threads waited + all done with iter it-1

        if (it + 1 < nit) {  // prefetch next stage (buffer last read at it-1)
            prefetch((it + 1) & 1, k0 + 128);
            CP_COMMIT();
        }

        const uint32_t stg = sb + SM_STG + (it & 1) * STG_STR;

#pragma unroll
        for (int kh2 = 0; kh2 < 2; kh2++) {
            const int kbase = kh2 * 64 + wk * 32;   // smem row base for this warp

            // ---- S(16x32) = Qh Kh^T : 1-term ----
            float sc[16];
#pragma unroll
            for (int i = 0; i < 16; i++) sc[i] = 0.0f;

#pragma unroll
            for (int kc = 0; kc < 4; kc++) {
#pragma unroll
                for (int nt4 = 0; nt4 < 2; nt4++) {
                    uint32_t row = kbase + nt4 * 16 + (lane & 7) + ((lane >> 4) << 3);
                    uint32_t offB = swz(row * 128 + (kc * 16 + ((lane >> 3) & 1) * 8) * 2);
                    uint32_t bh[4];
                    ldsm4(bh, stg + offB);
                    mma16816(&sc[nt4 * 8],     ah[kc], bh[0], bh[1]);
                    mma16816(&sc[nt4 * 8 + 4], ah[kc], bh[2], bh[3]);
                }
            }

            // ---- softmax (masked -> 0 exactly); single-fp16 P ----
            uint32_t pf[8];
#pragma unroll
            for (int nt = 0; nt < 4; nt++) {
                const int kg = k0 + kh2 * 64 + wk * 32 + nt * 8 + 2 * (lane & 3);
                float p0 = (kg     >= qg0) ? 0.0f : __expf(sc[nt * 4 + 0] * 0.125f);
                float p1 = (kg + 1 >= qg0) ? 0.0f : __expf(sc[nt * 4 + 1] * 0.125f);
                float p2 = (kg     >= qg1) ? 0.0f : __expf(sc[nt * 4 + 2] * 0.125f);
                float p3 = (kg + 1 >= qg1) ? 0.0f : __expf(sc[nt * 4 + 3] * 0.125f);
                l0 += p0 + p1;
                l1 += p2 + p3;
                pf[nt * 2 + 0] = pack2h(p0, p1);
                pf[nt * 2 + 1] = pack2h(p2, p3);
            }

            // ---- O(partial) += P V : 1-term ----
#pragma unroll
            for (int c = 0; c < 2; c++) {
                const uint32_t* pa = &pf[c * 4];
#pragma unroll
                for (int d4 = 0; d4 < 4; d4++) {
                    uint32_t rowV = kbase + c * 16 + (lane & 7) + ((lane >> 3) & 1) * 8;
                    uint32_t offV = swz(rowV * 128 + (d4 * 16 + (lane >> 4) * 8) * 2);
                    uint32_t bh[4];
                    ldsm4t(bh, stg + 16384 + offV);
                    mma16816(&Oa[d4 * 8],     pa, bh[0], bh[1]);
                    mma16816(&Oa[d4 * 8 + 4], pa, bh[2], bh[3]);
                }
            }
        }
        // no trailing sync — next iteration's top sync covers the hazard
    }
    __syncthreads();   // protect smem reduce region from in-flight readers

    // ---- Cross-warp (key-half) reduction via smem ----
    float* sred = reinterpret_cast<float*>(smc);   // [4][32][RED_STR]
    float* slot = sred + (wr * 32 + lane) * RED_STR;
    if (wk == 1) {
#pragma unroll
        for (int i = 0; i < 32; i++) slot[i] = Oa[i];
        slot[32] = l0;
        slot[33] = l1;
    }
    __syncthreads();
    if (wk == 0) {
#pragma unroll
        for (int i = 0; i < 32; i++) Oa[i] += slot[i];
        l0 += slot[32];
        l1 += slot[33];

        l0 += __shfl_xor_sync(0xffffffffu, l0, 1);
        l0 += __shfl_xor_sync(0xffffffffu, l0, 2);
        l1 += __shfl_xor_sync(0xffffffffu, l1, 1);
        l1 += __shfl_xor_sync(0xffffffffu, l1, 2);
        const float inv0 = (l0 > 0.0f) ? 1.0f / l0 : 0.0f;   // row 0 overwritten by meanv_fix
        const float inv1 = 1.0f / l1;

        const int row0 = q0 + wr * 16 + (lane >> 2);
        const size_t base0 = ((size_t)(b * SS + row0)) * DD + h * DQ;
        const size_t base1 = base0 + (size_t)8 * DD;
#pragma unroll
        for (int nt = 0; nt < 8; nt++) {
            const int col = nt * 8 + 2 * (lane & 3);
            *reinterpret_cast<uint32_t*>(&g_ctx_h[base0 + col]) =
                pack2h(Oa[nt * 4 + 0] * inv0, Oa[nt * 4 + 1] * inv0);
            *reinterpret_cast<uint32_t*>(&g_ctx_h[base1 + col]) =
                pack2h(Oa[nt * 4 + 2] * inv1, Oa[nt * 4 + 3] * inv1);
        }
    }
}

// ===========================================================================
// Projection (unchanged R12): 1-term fp16 GEMM, CTA 128x64, BK=64, 256 thr.
// ===========================================================================
#define PNIT (DD / 64)

extern "C" __global__ void __launch_bounds__(256, 2)
proj_mma2(const float* __restrict__ bias,
          float* __restrict__ out)
{
    __shared__ __align__(16) char sA[2][16384];
    __shared__ __align__(16) char sB[2][8192];

    const int tid  = threadIdx.x;
    const int lane = tid & 31;
    const int wid  = tid >> 5;
    const int wm   = wid >> 1;
    const int wn   = wid & 1;
    const int j0   = blockIdx.x * 64;
    const int i0   = blockIdx.y * 128;

    const uint32_t sa0 = smem_u32(sA[0]);
    const uint32_t sa1 = smem_u32(sA[1]);
    const uint32_t sb0 = smem_u32(sB[0]);
    const uint32_t sb1 = smem_u32(sB[1]);

    float acc[32];
#pragma unroll
    for (int i = 0; i < 32; i++) acc[i] = 0.0f;

    auto issue = [&](int stage, int k0) {
        const uint32_t sa = stage ? sa1 : sa0;
        const uint32_t sbm = stage ? sb1 : sb0;
#pragma unroll
        for (int q = 0; q < 4; q++) {
            int id = q * 256 + tid;
            int r = id >> 3;
            int g = id & 7;
            cpa16(sa + swz((uint32_t)(r * 128 + g * 16)),
                  &g_ctx_h[(size_t)(i0 + r) * DD + k0 + g * 8]);
        }
#pragma unroll
        for (int q = 0; q < 2; q++) {
            int id = q * 256 + tid;
            int r = id >> 3;
            int g = id & 7;
            cpa16(sbm + swz((uint32_t)(r * 128 + g * 16)),
                  &g_w_h[(size_t)(j0 + r) * DD + k0 + g * 8]);
        }
    };

    issue(0, 0);  CP_COMMIT();
    issue(1, 64); CP_COMMIT();

    for (int it = 0; it < PNIT; it++) {
        CP_WAIT1();
        __syncthreads();
        const uint32_t sa = (it & 1) ? sa1 : sa0;
        const uint32_t sbm = (it & 1) ? sb1 : sb0;

#pragma unroll
        for (int kc = 0; kc < 4; kc++) {
            uint32_t ah[2][4];
#pragma unroll
            for (int m = 0; m < 2; m++) {
                const uint32_t row = wm * 32 + m * 16 + (lane & 15);
                const uint32_t colb = (kc * 16 + (lane >> 4) * 8) * 2;
                ldsm4(ah[m], sa + swz(row * 128 + colb));
            }
            uint32_t bh[2][4];
#pragma unroll
            for (int nt = 0; nt < 2; nt++) {
                const uint32_t rowb = wn * 32 + nt * 16 + (lane & 7) + ((lane >> 4) << 3);
                const uint32_t colb = (kc * 16 + ((lane >> 3) & 1) * 8) * 2;
                ldsm4(bh[nt], sbm + swz(rowb * 128 + colb));
            }
#pragma unroll
            for (int m = 0; m < 2; m++)
#pragma unroll
                for (int nt = 0; nt < 2; nt++) {
                    float* c0 = &acc[(m * 2 + nt) * 8];
                    float* c1 = c0 + 4;
                    mma16816(c0, ah[m], bh[nt][0], bh[nt][1]);
                    mma16816(c1, ah[m], bh[nt][2], bh[nt][3]);
                }
        }

        __syncthreads();
        if (it + 2 < PNIT) {
            issue(it & 1, (it + 2) * 64);
        }
        CP_COMMIT();
    }

#pragma unroll
    for (int m = 0; m < 2; m++) {
        const int row = i0 + wm * 32 + m * 16 + (lane >> 2);
        float* d0 = out + (size_t)row * DD;
        float* d1 = d0 + (size_t)8 * DD;
#pragma unroll
        for (int nt = 0; nt < 2; nt++) {
#pragma unroll
            for (int n8 = 0; n8 < 2; n8++) {
                const int col = j0 + wn * 32 + nt * 16 + n8 * 8 + 2 * (lane & 3);
                const float* c = &acc[(m * 2 + nt) * 8 + n8 * 4];
                const float b0 = bias[col];
                const float b1 = bias[col + 1];
                *reinterpret_cast<float2*>(d0 + col) = make_float2(c[0] + b0, c[1] + b1);
                *reinterpret_cast<float2*>(d1 + col) = make_float2(c[2] + b0, c[3] + b1);
            }
        }
    }
}

// ===========================================================================
extern "C" void kernel_launch(void* const* d_in, const int* in_sizes, int n_in,
                              void* d_out, int out_size)
{
    const float* Q    = (const float*)d_in[0];
    const float* K    = (const float*)d_in[1];
    const float* V    = (const float*)d_in[2];
    const float* Wo_w = (const float*)d_in[3];
    const float* Wo_b = (const float*)d_in[4];

    convert_all<<<1152, 256>>>(K, V, Wo_w);

    cudaFuncSetAttribute(attn_mma, cudaFuncAttributeMaxDynamicSharedMemorySize, SMEM_BYTES);
    dim3 agrid(SS / BM, HH, BB);          // (32, 16, 2)
    attn_mma<<<agrid, 256, SMEM_BYTES>>>(Q);

    dim3 mgrid(HH, BB);
    meanv_fix<<<mgrid, 256>>>(V);

    dim3 pgrid(DD / 64, (BB * SS) / 128); // (16, 32)
    proj_mma2<<<pgrid, 256>>>(Wo_b, (float*)d_out);
}

// round 14
// speedup vs baseline: 1.0983x; 1.0983x over previous
#include <cuda_runtime.h>
#include <cuda_fp16.h>
#include <math.h>
#include <stdint.h>

// Problem constants
#define BB 2
#define SS 2048
#define DD 1024
#define HH 16
#define DQ 64

// Attention tiling
#define BM 64
#define BN 64

// ctx scratch (single fp16)
__device__ __half g_ctx_h[BB * SS * DD];
// W hi fp16
__device__ __half g_w_h[DD * DD];
// K hi; V hi (single fp16 each)
__device__ __half g_k_h[BB * SS * DD];
__device__ __half g_v_h[BB * SS * DD];

// ===========================================================================
// Helpers
// ===========================================================================
__device__ __forceinline__ uint32_t smem_u32(const void* p) {
    uint32_t a;
    asm("{ .reg .u64 t; cvta.to.shared.u64 t, %1; cvt.u32.u64 %0, t; }" : "=r"(a) : "l"(p));
    return a;
}
__device__ __forceinline__ uint32_t swz(uint32_t off) {
    return off ^ ((off >> 3) & 0x70);
}
__device__ __forceinline__ void ldsm4(uint32_t* r, uint32_t addr) {
    asm volatile("ldmatrix.sync.aligned.m8n8.x4.shared.b16 {%0,%1,%2,%3}, [%4];"
                 : "=r"(r[0]), "=r"(r[1]), "=r"(r[2]), "=r"(r[3]) : "r"(addr));
}
__device__ __forceinline__ void ldsm4t(uint32_t* r, uint32_t addr) {
    asm volatile("ldmatrix.sync.aligned.m8n8.x4.trans.shared.b16 {%0,%1,%2,%3}, [%4];"
                 : "=r"(r[0]), "=r"(r[1]), "=r"(r[2]), "=r"(r[3]) : "r"(addr));
}
__device__ __forceinline__ void mma16816(float* c, const uint32_t* a, uint32_t b0, uint32_t b1) {
    asm volatile("mma.sync.aligned.m16n8k16.row.col.f32.f16.f16.f32 "
                 "{%0,%1,%2,%3}, {%4,%5,%6,%7}, {%8,%9}, {%0,%1,%2,%3};"
                 : "+f"(c[0]), "+f"(c[1]), "+f"(c[2]), "+f"(c[3])
                 : "r"(a[0]), "r"(a[1]), "r"(a[2]), "r"(a[3]), "r"(b0), "r"(b1));
}
__device__ __forceinline__ uint2 pack4h(float4 v) {
    __half2 a = __floats2half2_rn(v.x, v.y);
    __half2 b = __floats2half2_rn(v.z, v.w);
    uint2 r;
    r.x = *reinterpret_cast<uint32_t*>(&a);
    r.y = *reinterpret_cast<uint32_t*>(&b);
    return r;
}
__device__ __forceinline__ uint32_t pack2h(float x, float y) {
    __half2 h = __floats2half2_rn(x, y);
    return *reinterpret_cast<uint32_t*>(&h);
}
__device__ __forceinline__ void cpa16(uint32_t d, const void* s) {
    asm volatile("cp.async.cg.shared.global [%0], [%1], 16;" :: "r"(d), "l"(s));
}
#define CP_COMMIT() asm volatile("cp.async.commit_group;" ::: "memory")
#define CP_WAIT0()  asm volatile("cp.async.wait_group 0;" ::: "memory")
#define CP_WAIT1()  asm volatile("cp.async.wait_group 1;" ::: "memory")

// ===========================================================================
// Fused converter + row-0 fix:
//   blocks [0,512)     K -> fp16 hi
//   blocks [512,1024)  V -> fp16 hi
//   blocks [1024,1152) W -> fp16 hi
//   blocks [1152,1184) meanv: ctx(q=0) = mean_s V  (fully-masked row)
// ===========================================================================
extern "C" __global__ void __launch_bounds__(256)
convert_all(const float* __restrict__ K,
            const float* __restrict__ V,
            const float* __restrict__ W)
{
    __shared__ float red[256];
    const int bid = blockIdx.x;
    const int tid = threadIdx.x;

    if (bid < 1152) {
        float4 v[8];
        if (bid < 512) {
            int i0 = (bid * 256 + tid) * 8;
#pragma unroll
            for (int j = 0; j < 8; j++) v[j] = reinterpret_cast<const float4*>(K)[i0 + j];
#pragma unroll
            for (int j = 0; j < 4; j++) {
                uint2 a = pack4h(v[2 * j]), b = pack4h(v[2 * j + 1]);
                reinterpret_cast<uint4*>(g_k_h)[i0 / 2 + j] = make_uint4(a.x, a.y, b.x, b.y);
            }
        } else if (bid < 1024) {
            int i0 = ((bid - 512) * 256 + tid) * 8;
#pragma unroll
            for (int j = 0; j < 8; j++) v[j] = reinterpret_cast<const float4*>(V)[i0 + j];
#pragma unroll
            for (int j = 0; j < 4; j++) {
                uint2 a = pack4h(v[2 * j]), b = pack4h(v[2 * j + 1]);
                reinterpret_cast<uint4*>(g_v_h)[i0 / 2 + j] = make_uint4(a.x, a.y, b.x, b.y);
            }
        } else {
            int i0 = ((bid - 1024) * 256 + tid) * 8;
#pragma unroll
            for (int j = 0; j < 8; j++) v[j] = reinterpret_cast<const float4*>(W)[i0 + j];
#pragma unroll
            for (int j = 0; j < 4; j++) {
                uint2 a = pack4h(v[2 * j]), b = pack4h(v[2 * j + 1]);
                reinterpret_cast<uint4*>(g_w_h)[i0 / 2 + j] = make_uint4(a.x, a.y, b.x, b.y);
            }
        }
    } else {
        // meanv: ctx row 0 = mean over all 2048 keys of V (per b, h)
        const int idx = bid - 1152;
        const int h = idx & 15;
        const int b = idx >> 4;
        const int d = tid & 63;
        const int sc = tid >> 6;
        const float* src = V + (size_t)b * SS * DD + h * DQ + d;
        float s = 0.0f;
#pragma unroll 8
        for (int i = sc * 512; i < sc * 512 + 512; i++)
            s += src[(size_t)i * DD];
        red[tid] = s;
        __syncthreads();
        if (tid < 64) {
            float m = (red[tid] + red[tid + 64] + red[tid + 128] + red[tid + 192]) * (1.0f / 2048.0f);
            g_ctx_h[(size_t)b * SS * DD + h * DQ + d] = __float2half_rn(m);
        }
    }
}

// ===========================================================================
// Attention smem: Q hi (8 KB) + 2 stages x (KH, VH) (16 KB each) = 40 KB.
// Cross-warp reduce buffer reuses [0, ~18 KB) after the main loop.
// ===========================================================================
#define SM_QH   0
#define SM_STG  8192
#define STG_STR 16384
#define SMEM_BYTES 40960
#define RED_STR 35

// ===========================================================================
// Flash attention (R12-proven): fp16 HMMA, pipelined K/V, 8 warps
// (16 rows x 32 keys). QK 1-term (Q frags hoisted), PV 1-term.
// Row-0 store skipped (meanv owns it). Grid (32,16,2), 256 threads.
// ===========================================================================
extern "C" __global__ void __launch_bounds__(256, 2)
attn_mma(const float* __restrict__ Q)
{
    extern __shared__ char smc[];
    const uint32_t sb = smem_u32(smc);
    const int tid  = threadIdx.x;
    const int lane = tid & 31;
    const int wid  = tid >> 5;
    const int wr   = wid >> 1;    // row group 0..3
    const int wk   = wid & 1;     // key half 0..1

    const int bx = blockIdx.x;
    const int qt = (bx == 31) ? 0 : (31 - bx);
    const int h  = blockIdx.y;
    const int b  = blockIdx.z;
    const int q0 = qt * BM;

    const float* Qb  = Q + ((size_t)(b * SS + q0)) * DD + h * DQ;
    const size_t kvb = (size_t)b * SS * DD + h * DQ;

    const int nkt = qt + 1;

    auto prefetch = [&](int stage, int k0) {
        const uint32_t stg = sb + SM_STG + stage * STG_STR;
#pragma unroll
        for (int q = 0; q < 2; q++) {
            const int id = q * 256 + tid;     // 0..511
            const int r = id >> 3;
            const int g = id & 7;
            const uint32_t off = swz((uint32_t)(r * 128 + g * 16));
            const size_t srco = kvb + (size_t)(k0 + r) * DD + g * 8;
            cpa16(stg + off,        &g_k_h[srco]);
            cpa16(stg + 8192 + off, &g_v_h[srco]);
        }
    };

    prefetch(0, 0);
    CP_COMMIT();

    // ---- Load Q tile (hi only; overlaps stage-0 prefetch) ----
#pragma unroll
    for (int it = 0; it < 4; it++) {
        int idx = it * 256 + tid;
        int r = idx >> 4;
        int g = idx & 15;
        float4 q4 = *reinterpret_cast<const float4*>(Qb + (size_t)r * DD + g * 4);
        uint32_t off = swz((uint32_t)(r * 128 + g * 8));
        *reinterpret_cast<uint2*>(smc + SM_QH + off) = pack4h(q4);
    }
    __syncthreads();

    // ---- Hoist Q fragments (loop-invariant across k-tiles) ----
    uint32_t ah[4][4];
#pragma unroll
    for (int kc = 0; kc < 4; kc++) {
        uint32_t offA = swz((uint32_t)((wr * 16 + (lane & 15)) * 128 +
                                       (kc * 16 + (lane >> 4) * 8) * 2));
        ldsm4(ah[kc], sb + SM_QH + offA);
    }

    float Oa[32];
    float l0 = 0.0f, l1 = 0.0f;
#pragma unroll
    for (int i = 0; i < 32; i++) Oa[i] = 0.0f;

    const int qg0 = q0 + wr * 16 + (lane >> 2);
    const int qg1 = qg0 + 8;

    for (int kt = 0; kt < nkt; kt++) {
        const int k0 = kt * BN;

        if (kt + 1 < nkt) {
            prefetch((kt + 1) & 1, k0 + BN);
            CP_COMMIT();
            CP_WAIT1();
        } else {
            CP_WAIT0();
        }
        __syncthreads();

        const uint32_t stg = sb + SM_STG + (kt & 1) * STG_STR;

        // ---- S(16x32) = Qh Kh^T : 1-term ----
        float sc[16];
#pragma unroll
        for (int i = 0; i < 16; i++) sc[i] = 0.0f;

#pragma unroll
        for (int kc = 0; kc < 4; kc++) {
#pragma unroll
            for (int nt4 = 0; nt4 < 2; nt4++) {
                uint32_t offB = swz((uint32_t)((wk * 32 + nt4 * 16 + (lane & 7) + ((lane >> 4) << 3)) * 128 +
                                               (kc * 16 + ((lane >> 3) & 1) * 8) * 2));
                uint32_t bh[4];
                ldsm4(bh, stg + offB);
                mma16816(&sc[nt4 * 8],     ah[kc], bh[0], bh[1]);
                mma16816(&sc[nt4 * 8 + 4], ah[kc], bh[2], bh[3]);
            }
        }

        // ---- softmax (masked -> 0 exactly); single-fp16 P ----
        uint32_t pf[8];
#pragma unroll
        for (int nt = 0; nt < 4; nt++) {
            const int kg = k0 + wk * 32 + nt * 8 + 2 * (lane & 3);
            float p0 = (kg     >= qg0) ? 0.0f : __expf(sc[nt * 4 + 0] * 0.125f);
            float p1 = (kg + 1 >= qg0) ? 0.0f : __expf(sc[nt * 4 + 1] * 0.125f);
            float p2 = (kg     >= qg1) ? 0.0f : __expf(sc[nt * 4 + 2] * 0.125f);
            float p3 = (kg + 1 >= qg1) ? 0.0f : __expf(sc[nt * 4 + 3] * 0.125f);
            l0 += p0 + p1;
            l1 += p2 + p3;
            pf[nt * 2 + 0] = pack2h(p0, p1);
            pf[nt * 2 + 1] = pack2h(p2, p3);
        }

        // ---- O(partial over key-half) += P V : 1-term ----
#pragma unroll
        for (int c = 0; c < 2; c++) {
            const uint32_t* pa = &pf[c * 4];
#pragma unroll
            for (int d4 = 0; d4 < 4; d4++) {
                uint32_t offV = swz((uint32_t)((wk * 32 + c * 16 + (lane & 7) + ((lane >> 3) & 1) * 8) * 128 +
                                               (d4 * 16 + (lane >> 4) * 8) * 2));
                uint32_t bh[4];
                ldsm4t(bh, stg + 8192 + offV);
                mma16816(&Oa[d4 * 8],     pa, bh[0], bh[1]);
                mma16816(&Oa[d4 * 8 + 4], pa, bh[2], bh[3]);
            }
        }
        __syncthreads();
    }

    // ---- Cross-warp (key-half) reduction via smem ----
    float* sred = reinterpret_cast<float*>(smc);   // [4][32][RED_STR]
    float* slot = sred + (wr * 32 + lane) * RED_STR;
    if (wk == 1) {
#pragma unroll
        for (int i = 0; i < 32; i++) slot[i] = Oa[i];
        slot[32] = l0;
        slot[33] = l1;
    }
    __syncthreads();
    if (wk == 0) {
#pragma unroll
        for (int i = 0; i < 32; i++) Oa[i] += slot[i];
        l0 += slot[32];
        l1 += slot[33];

        l0 += __shfl_xor_sync(0xffffffffu, l0, 1);
        l0 += __shfl_xor_sync(0xffffffffu, l0, 2);
        l1 += __shfl_xor_sync(0xffffffffu, l1, 1);
        l1 += __shfl_xor_sync(0xffffffffu, l1, 2);
        const float inv0 = (l0 > 0.0f) ? 1.0f / l0 : 0.0f;
        const float inv1 = 1.0f / l1;

        const int row0 = q0 + wr * 16 + (lane >> 2);
        const size_t base0 = ((size_t)(b * SS + row0)) * DD + h * DQ;
        const size_t base1 = base0 + (size_t)8 * DD;
#pragma unroll
        for (int nt = 0; nt < 8; nt++) {
            const int col = nt * 8 + 2 * (lane & 3);
            if (row0 != 0) {   // row 0 owned by meanv (runs in convert_all)
                *reinterpret_cast<uint32_t*>(&g_ctx_h[base0 + col]) =
                    pack2h(Oa[nt * 4 + 0] * inv0, Oa[nt * 4 + 1] * inv0);
            }
            *reinterpret_cast<uint32_t*>(&g_ctx_h[base1 + col]) =
                pack2h(Oa[nt * 4 + 2] * inv1, Oa[nt * 4 + 3] * inv1);
        }
    }
}

// ===========================================================================
// Projection (unchanged R12): 1-term fp16 GEMM, CTA 128x64, BK=64, 256 thr.
// ===========================================================================
#define PNIT (DD / 64)

extern "C" __global__ void __launch_bounds__(256, 2)
proj_mma2(const float* __restrict__ bias,
          float* __restrict__ out)
{
    __shared__ __align__(16) char sA[2][16384];
    __shared__ __align__(16) char sB[2][8192];

    const int tid  = threadIdx.x;
    const int lane = tid & 31;
    const int wid  = tid >> 5;
    const int wm   = wid >> 1;
    const int wn   = wid & 1;
    const int j0   = blockIdx.x * 64;
    const int i0   = blockIdx.y * 128;

    const uint32_t sa0 = smem_u32(sA[0]);
    const uint32_t sa1 = smem_u32(sA[1]);
    const uint32_t sb0 = smem_u32(sB[0]);
    const uint32_t sb1 = smem_u32(sB[1]);

    float acc[32];
#pragma unroll
    for (int i = 0; i < 32; i++) acc[i] = 0.0f;

    auto issue = [&](int stage, int k0) {
        const uint32_t sa = stage ? sa1 : sa0;
        const uint32_t sbm = stage ? sb1 : sb0;
#pragma unroll
        for (int q = 0; q < 4; q++) {
            int id = q * 256 + tid;
            int r = id >> 3;
            int g = id & 7;
            cpa16(sa + swz((uint32_t)(r * 128 + g * 16)),
                  &g_ctx_h[(size_t)(i0 + r) * DD + k0 + g * 8]);
        }
#pragma unroll
        for (int q = 0; q < 2; q++) {
            int id = q * 256 + tid;
            int r = id >> 3;
            int g = id & 7;
            cpa16(sbm + swz((uint32_t)(r * 128 + g * 16)),
                  &g_w_h[(size_t)(j0 + r) * DD + k0 + g * 8]);
        }
    };

    issue(0, 0);  CP_COMMIT();
    issue(1, 64); CP_COMMIT();

    for (int it = 0; it < PNIT; it++) {
        CP_WAIT1();
        __syncthreads();
        const uint32_t sa = (it & 1) ? sa1 : sa0;
        const uint32_t sbm = (it & 1) ? sb1 : sb0;

#pragma unroll
        for (int kc = 0; kc < 4; kc++) {
            uint32_t ah[2][4];
#pragma unroll
            for (int m = 0; m < 2; m++) {
                const uint32_t row = wm * 32 + m * 16 + (lane & 15);
                const uint32_t colb = (kc * 16 + (lane >> 4) * 8) * 2;
                ldsm4(ah[m], sa + swz(row * 128 + colb));
            }
            uint32_t bh[2][4];
#pragma unroll
            for (int nt = 0; nt < 2; nt++) {
                const uint32_t rowb = wn * 32 + nt * 16 + (lane & 7) + ((lane >> 4) << 3);
                const uint32_t colb = (kc * 16 + ((lane >> 3) & 1) * 8) * 2;
                ldsm4(bh[nt], sbm + swz(rowb * 128 + colb));
            }
#pragma unroll
            for (int m = 0; m < 2; m++)
#pragma unroll
                for (int nt = 0; nt < 2; nt++) {
                    float* c0 = &acc[(m * 2 + nt) * 8];
                    float* c1 = c0 + 4;
                    mma16816(c0, ah[m], bh[nt][0], bh[nt][1]);
                    mma16816(c1, ah[m], bh[nt][2], bh[nt][3]);
                }
        }

        __syncthreads();
        if (it + 2 < PNIT) {
            issue(it & 1, (it + 2) * 64);
        }
        CP_COMMIT();
    }

#pragma unroll
    for (int m = 0; m < 2; m++) {
        const int row = i0 + wm * 32 + m * 16 + (lane >> 2);
        float* d0 = out + (size_t)row * DD;
        float* d1 = d0 + (size_t)8 * DD;
#pragma unroll
        for (int nt = 0; nt < 2; nt++) {
#pragma unroll
            for (int n8 = 0; n8 < 2; n8++) {
                const int col = j0 + wn * 32 + nt * 16 + n8 * 8 + 2 * (lane & 3);
                const float* c = &acc[(m * 2 + nt) * 8 + n8 * 4];
                const float b0 = bias[col];
                const float b1 = bias[col + 1];
                *reinterpret_cast<float2*>(d0 + col) = make_float2(c[0] + b0, c[1] + b1);
                *reinterpret_cast<float2*>(d1 + col) = make_float2(c[2] + b0, c[3] + b1);
            }
        }
    }
}

// ===========================================================================
extern "C" void kernel_launch(void* const* d_in, const int* in_sizes, int n_in,
                              void* d_out, int out_size)
{
    const float* Q    = (const float*)d_in[0];
    const float* K    = (const float*)d_in[1];
    const float* V    = (const float*)d_in[2];
    const float* Wo_w = (const float*)d_in[3];
    const float* Wo_b = (const float*)d_in[4];

    convert_all<<<1184, 256>>>(K, V, Wo_w);   // converts + meanv fused

    cudaFuncSetAttribute(attn_mma, cudaFuncAttributeMaxDynamicSharedMemorySize, SMEM_BYTES);
    dim3 agrid(SS / BM, HH, BB);          // (32, 16, 2)
    attn_mma<<<agrid, 256, SMEM_BYTES>>>(Q);

    dim3 pgrid(DD / 64, (BB * SS) / 128); // (16, 32)
    proj_mma2<<<pgrid, 256>>>(Wo_b, (float*)d_out);
}

// round 15
// speedup vs baseline: 1.1351x; 1.0336x over previous
#include <cuda_runtime.h>
#include <cuda_fp16.h>
#include <math.h>
#include <stdint.h>

// Problem constants
#define BB 2
#define SS 2048
#define DD 1024
#define HH 16
#define DQ 64

// Attention tiling
#define BM 64
#define BN 64

// ctx scratch (single fp16)
__device__ __half g_ctx_h[BB * SS * DD];
// W hi fp16
__device__ __half g_w_h[DD * DD];
// K hi; V hi (single fp16 each)
__device__ __half g_k_h[BB * SS * DD];
__device__ __half g_v_h[BB * SS * DD];

// ===========================================================================
// Helpers
// ===========================================================================
__device__ __forceinline__ uint32_t smem_u32(const void* p) {
    uint32_t a;
    asm("{ .reg .u64 t; cvta.to.shared.u64 t, %1; cvt.u32.u64 %0, t; }" : "=r"(a) : "l"(p));
    return a;
}
__device__ __forceinline__ uint32_t swz(uint32_t off) {
    return off ^ ((off >> 3) & 0x70);
}
__device__ __forceinline__ void ldsm4(uint32_t* r, uint32_t addr) {
    asm volatile("ldmatrix.sync.aligned.m8n8.x4.shared.b16 {%0,%1,%2,%3}, [%4];"
                 : "=r"(r[0]), "=r"(r[1]), "=r"(r[2]), "=r"(r[3]) : "r"(addr));
}
__device__ __forceinline__ void ldsm4t(uint32_t* r, uint32_t addr) {
    asm volatile("ldmatrix.sync.aligned.m8n8.x4.trans.shared.b16 {%0,%1,%2,%3}, [%4];"
                 : "=r"(r[0]), "=r"(r[1]), "=r"(r[2]), "=r"(r[3]) : "r"(addr));
}
__device__ __forceinline__ void mma16816(float* c, const uint32_t* a, uint32_t b0, uint32_t b1) {
    asm volatile("mma.sync.aligned.m16n8k16.row.col.f32.f16.f16.f32 "
                 "{%0,%1,%2,%3}, {%4,%5,%6,%7}, {%8,%9}, {%0,%1,%2,%3};"
                 : "+f"(c[0]), "+f"(c[1]), "+f"(c[2]), "+f"(c[3])
                 : "r"(a[0]), "r"(a[1]), "r"(a[2]), "r"(a[3]), "r"(b0), "r"(b1));
}
__device__ __forceinline__ uint2 pack4h(float4 v) {
    __half2 a = __floats2half2_rn(v.x, v.y);
    __half2 b = __floats2half2_rn(v.z, v.w);
    uint2 r;
    r.x = *reinterpret_cast<uint32_t*>(&a);
    r.y = *reinterpret_cast<uint32_t*>(&b);
    return r;
}
__device__ __forceinline__ uint32_t pack2h(float x, float y) {
    __half2 h = __floats2half2_rn(x, y);
    return *reinterpret_cast<uint32_t*>(&h);
}
__device__ __forceinline__ void cpa16(uint32_t d, const void* s) {
    asm volatile("cp.async.cg.shared.global [%0], [%1], 16;" :: "r"(d), "l"(s));
}
#define CP_COMMIT() asm volatile("cp.async.commit_group;" ::: "memory")
#define CP_WAIT0()  asm volatile("cp.async.wait_group 0;" ::: "memory")
#define CP_WAIT1()  asm volatile("cp.async.wait_group 1;" ::: "memory")

// exp2 constant: 0.125 (scale) * log2(e)
#define EXPC 0.1803368801111244f

// ===========================================================================
// Fused converter + row-0 fix (COALESCED):
//   blocks [0,512)     K -> fp16   (512 * 1024 uint4 outputs)
//   blocks [512,1024)  V -> fp16
//   blocks [1024,1152) W -> fp16   (128 * 1024 uint4 outputs)
//   blocks [1152,1184) meanv: ctx(q=0) = mean_s V
// Thread t, chunk j: output uint4 o = base + j*256 + t; reads float4 2o, 2o+1.
// Warp-contiguous: 1 KB/instr loads, 512 B/instr stores.
// ===========================================================================
extern "C" __global__ void __launch_bounds__(256)
convert_all(const float* __restrict__ K,
            const float* __restrict__ V,
            const float* __restrict__ W)
{
    __shared__ float red[256];
    const int bid = blockIdx.x;
    const int tid = threadIdx.x;

    if (bid < 1152) {
        const float4* src;
        uint4* dst;
        int base;
        if (bid < 512) {
            src = reinterpret_cast<const float4*>(K);
            dst = reinterpret_cast<uint4*>(g_k_h);
            base = bid * 1024;
        } else if (bid < 1024) {
            src = reinterpret_cast<const float4*>(V);
            dst = reinterpret_cast<uint4*>(g_v_h);
            base = (bid - 512) * 1024;
        } else {
            src = reinterpret_cast<const float4*>(W);
            dst = reinterpret_cast<uint4*>(g_w_h);
            base = (bid - 1024) * 1024;
        }
        float4 a[4], b[4];
#pragma unroll
        for (int j = 0; j < 4; j++) {
            const int o = base + j * 256 + tid;
            a[j] = src[2 * o];
            b[j] = src[2 * o + 1];
        }
#pragma unroll
        for (int j = 0; j < 4; j++) {
            const int o = base + j * 256 + tid;
            uint2 pa = pack4h(a[j]), pb = pack4h(b[j]);
            dst[o] = make_uint4(pa.x, pa.y, pb.x, pb.y);
        }
    } else {
        // meanv: ctx row 0 = mean over all 2048 keys of V (per b, h)
        const int idx = bid - 1152;
        const int h = idx & 15;
        const int b = idx >> 4;
        const int d = tid & 63;
        const int sc = tid >> 6;
        const float* src = V + (size_t)b * SS * DD + h * DQ + d;
        float s = 0.0f;
#pragma unroll 8
        for (int i = sc * 512; i < sc * 512 + 512; i++)
            s += src[(size_t)i * DD];
        red[tid] = s;
        __syncthreads();
        if (tid < 64) {
            float m = (red[tid] + red[tid + 64] + red[tid + 128] + red[tid + 192]) * (1.0f / 2048.0f);
            g_ctx_h[(size_t)b * SS * DD + h * DQ + d] = __float2half_rn(m);
        }
    }
}

// ===========================================================================
// Attention smem: Q hi (8 KB) + 2 stages x (KH, VH) (16 KB each) = 40 KB.
// Cross-warp reduce buffer reuses [0, ~18 KB) after the main loop.
// ===========================================================================
#define SM_QH   0
#define SM_STG  8192
#define STG_STR 16384
#define SMEM_BYTES 40960
#define RED_STR 35

// ===========================================================================
// Flash attention (R12-proven): fp16 HMMA, pipelined K/V, 8 warps
// (16 rows x 32 keys). QK 1-term (Q frags hoisted), PV 1-term.
// Row-0 store skipped (meanv owns it). Grid (32,16,2), 256 threads.
// ===========================================================================
extern "C" __global__ void __launch_bounds__(256, 2)
attn_mma(const float* __restrict__ Q)
{
    extern __shared__ char smc[];
    const uint32_t sb = smem_u32(smc);
    const int tid  = threadIdx.x;
    const int lane = tid & 31;
    const int wid  = tid >> 5;
    const int wr   = wid >> 1;    // row group 0..3
    const int wk   = wid & 1;     // key half 0..1

    const int bx = blockIdx.x;
    const int qt = (bx == 31) ? 0 : (31 - bx);
    const int h  = blockIdx.y;
    const int b  = blockIdx.z;
    const int q0 = qt * BM;

    const float* Qb  = Q + ((size_t)(b * SS + q0)) * DD + h * DQ;
    const size_t kvb = (size_t)b * SS * DD + h * DQ;

    const int nkt = qt + 1;

    auto prefetch = [&](int stage, int k0) {
        const uint32_t stg = sb + SM_STG + stage * STG_STR;
#pragma unroll
        for (int q = 0; q < 2; q++) {
            const int id = q * 256 + tid;     // 0..511
            const int r = id >> 3;
            const int g = id & 7;
            const uint32_t off = swz((uint32_t)(r * 128 + g * 16));
            const size_t srco = kvb + (size_t)(k0 + r) * DD + g * 8;
            cpa16(stg + off,        &g_k_h[srco]);
            cpa16(stg + 8192 + off, &g_v_h[srco]);
        }
    };

    prefetch(0, 0);
    CP_COMMIT();

    // ---- Load Q tile (hi only; overlaps stage-0 prefetch) ----
#pragma unroll
    for (int it = 0; it < 4; it++) {
        int idx = it * 256 + tid;
        int r = idx >> 4;
        int g = idx & 15;
        float4 q4 = *reinterpret_cast<const float4*>(Qb + (size_t)r * DD + g * 4);
        uint32_t off = swz((uint32_t)(r * 128 + g * 8));
        *reinterpret_cast<uint2*>(smc + SM_QH + off) = pack4h(q4);
    }
    __syncthreads();

    // ---- Hoist Q fragments (loop-invariant across k-tiles) ----
    uint32_t ah[4][4];
#pragma unroll
    for (int kc = 0; kc < 4; kc++) {
        uint32_t offA = swz((uint32_t)((wr * 16 + (lane & 15)) * 128 +
                                       (kc * 16 + (lane >> 4) * 8) * 2));
        ldsm4(ah[kc], sb + SM_QH + offA);
    }

    float Oa[32];
    float l0 = 0.0f, l1 = 0.0f;
#pragma unroll
    for (int i = 0; i < 32; i++) Oa[i] = 0.0f;

    const int qg0 = q0 + wr * 16 + (lane >> 2);
    const int qg1 = qg0 + 8;

    for (int kt = 0; kt < nkt; kt++) {
        const int k0 = kt * BN;

        if (kt + 1 < nkt) {
            prefetch((kt + 1) & 1, k0 + BN);
            CP_COMMIT();
            CP_WAIT1();
        } else {
            CP_WAIT0();
        }
        __syncthreads();

        const uint32_t stg = sb + SM_STG + (kt & 1) * STG_STR;

        // ---- S(16x32) = Qh Kh^T : 1-term ----
        float sc[16];
#pragma unroll
        for (int i = 0; i < 16; i++) sc[i] = 0.0f;

#pragma unroll
        for (int kc = 0; kc < 4; kc++) {
#pragma unroll
            for (int nt4 = 0; nt4 < 2; nt4++) {
                uint32_t offB = swz((uint32_t)((wk * 32 + nt4 * 16 + (lane & 7) + ((lane >> 4) << 3)) * 128 +
                                               (kc * 16 + ((lane >> 3) & 1) * 8) * 2));
                uint32_t bh[4];
                ldsm4(bh, stg + offB);
                mma16816(&sc[nt4 * 8],     ah[kc], bh[0], bh[1]);
                mma16816(&sc[nt4 * 8 + 4], ah[kc], bh[2], bh[3]);
            }
        }

        // ---- softmax (masked -> 0 exactly); single-fp16 P ----
        uint32_t pf[8];
#pragma unroll
        for (int nt = 0; nt < 4; nt++) {
            const int kg = k0 + wk * 32 + nt * 8 + 2 * (lane & 3);
            float p0 = (kg     >= qg0) ? 0.0f : exp2f(sc[nt * 4 + 0] * EXPC);
            float p1 = (kg + 1 >= qg0) ? 0.0f : exp2f(sc[nt * 4 + 1] * EXPC);
            float p2 = (kg     >= qg1) ? 0.0f : exp2f(sc[nt * 4 + 2] * EXPC);
            float p3 = (kg + 1 >= qg1) ? 0.0f : exp2f(sc[nt * 4 + 3] * EXPC);
            l0 += p0 + p1;
            l1 += p2 + p3;
            pf[nt * 2 + 0] = pack2h(p0, p1);
            pf[nt * 2 + 1] = pack2h(p2, p3);
        }

        // ---- O(partial over key-half) += P V : 1-term ----
#pragma unroll
        for (int c = 0; c < 2; c++) {
            const uint32_t* pa = &pf[c * 4];
#pragma unroll
            for (int d4 = 0; d4 < 4; d4++) {
                uint32_t offV = swz((uint32_t)((wk * 32 + c * 16 + (lane & 7) + ((lane >> 3) & 1) * 8) * 128 +
                                               (d4 * 16 + (lane >> 4) * 8) * 2));
                uint32_t bh[4];
                ldsm4t(bh, stg + 8192 + offV);
                mma16816(&Oa[d4 * 8],     pa, bh[0], bh[1]);
                mma16816(&Oa[d4 * 8 + 4], pa, bh[2], bh[3]);
            }
        }
        __syncthreads();
    }

    // ---- Cross-warp (key-half) reduction via smem ----
    float* sred = reinterpret_cast<float*>(smc);   // [4][32][RED_STR]
    float* slot = sred + (wr * 32 + lane) * RED_STR;
    if (wk == 1) {
#pragma unroll
        for (int i = 0; i < 32; i++) slot[i] = Oa[i];
        slot[32] = l0;
        slot[33] = l1;
    }
    __syncthreads();
    if (wk == 0) {
#pragma unroll
        for (int i = 0; i < 32; i++) Oa[i] += slot[i];
        l0 += slot[32];
        l1 += slot[33];

        l0 += __shfl_xor_sync(0xffffffffu, l0, 1);
        l0 += __shfl_xor_sync(0xffffffffu, l0, 2);
        l1 += __shfl_xor_sync(0xffffffffu, l1, 1);
        l1 += __shfl_xor_sync(0xffffffffu, l1, 2);
        const float inv0 = (l0 > 0.0f) ? 1.0f / l0 : 0.0f;
        const float inv1 = 1.0f / l1;

        const int row0 = q0 + wr * 16 + (lane >> 2);
        const size_t base0 = ((size_t)(b * SS + row0)) * DD + h * DQ;
        const size_t base1 = base0 + (size_t)8 * DD;
#pragma unroll
        for (int nt = 0; nt < 8; nt++) {
            const int col = nt * 8 + 2 * (lane & 3);
            if (row0 != 0) {   // row 0 owned by meanv (runs in convert_all)
                *reinterpret_cast<uint32_t*>(&g_ctx_h[base0 + col]) =
                    pack2h(Oa[nt * 4 + 0] * inv0, Oa[nt * 4 + 1] * inv0);
            }
            *reinterpret_cast<uint32_t*>(&g_ctx_h[base1 + col]) =
                pack2h(Oa[nt * 4 + 2] * inv1, Oa[nt * 4 + 3] * inv1);
        }
    }
}

// ===========================================================================
// Projection (unchanged R12): 1-term fp16 GEMM, CTA 128x64, BK=64, 256 thr.
// ===========================================================================
#define PNIT (DD / 64)

extern "C" __global__ void __launch_bounds__(256, 2)
proj_mma2(const float* __restrict__ bias,
          float* __restrict__ out)
{
    __shared__ __align__(16) char sA[2][16384];
    __shared__ __align__(16) char sB[2][8192];

    const int tid  = threadIdx.x;
    const int lane = tid & 31;
    const int wid  = tid >> 5;
    const int wm   = wid >> 1;
    const int wn   = wid & 1;
    const int j0   = blockIdx.x * 64;
    const int i0   = blockIdx.y * 128;

    const uint32_t sa0 = smem_u32(sA[0]);
    const uint32_t sa1 = smem_u32(sA[1]);
    const uint32_t sb0 = smem_u32(sB[0]);
    const uint32_t sb1 = smem_u32(sB[1]);

    float acc[32];
#pragma unroll
    for (int i = 0; i < 32; i++) acc[i] = 0.0f;

    auto issue = [&](int stage, int k0) {
        const uint32_t sa = stage ? sa1 : sa0;
        const uint32_t sbm = stage ? sb1 : sb0;
#pragma unroll
        for (int q = 0; q < 4; q++) {
            int id = q * 256 + tid;
            int r = id >> 3;
            int g = id & 7;
            cpa16(sa + swz((uint32_t)(r * 128 + g * 16)),
                  &g_ctx_h[(size_t)(i0 + r) * DD + k0 + g * 8]);
        }
#pragma unroll
        for (int q = 0; q < 2; q++) {
            int id = q * 256 + tid;
            int r = id >> 3;
            int g = id & 7;
            cpa16(sbm + swz((uint32_t)(r * 128 + g * 16)),
                  &g_w_h[(size_t)(j0 + r) * DD + k0 + g * 8]);
        }
    };

    issue(0, 0);  CP_COMMIT();
    issue(1, 64); CP_COMMIT();

    for (int it = 0; it < PNIT; it++) {
        CP_WAIT1();
        __syncthreads();
        const uint32_t sa = (it & 1) ? sa1 : sa0;
        const uint32_t sbm = (it & 1) ? sb1 : sb0;

#pragma unroll
        for (int kc = 0; kc < 4; kc++) {
            uint32_t ah[2][4];
#pragma unroll
            for (int m = 0; m < 2; m++) {
                const uint32_t row = wm * 32 + m * 16 + (lane & 15);
                const uint32_t colb = (kc * 16 + (lane >> 4) * 8) * 2;
                ldsm4(ah[m], sa + swz(row * 128 + colb));
            }
            uint32_t bh[2][4];
#pragma unroll
            for (int nt = 0; nt < 2; nt++) {
                const uint32_t rowb = wn * 32 + nt * 16 + (lane & 7) + ((lane >> 4) << 3);
                const uint32_t colb = (kc * 16 + ((lane >> 3) & 1) * 8) * 2;
                ldsm4(bh[nt], sbm + swz(rowb * 128 + colb));
            }
#pragma unroll
            for (int m = 0; m < 2; m++)
#pragma unroll
                for (int nt = 0; nt < 2; nt++) {
                    float* c0 = &acc[(m * 2 + nt) * 8];
                    float* c1 = c0 + 4;
                    mma16816(c0, ah[m], bh[nt][0], bh[nt][1]);
                    mma16816(c1, ah[m], bh[nt][2], bh[nt][3]);
                }
        }

        __syncthreads();
        if (it + 2 < PNIT) {
            issue(it & 1, (it + 2) * 64);
        }
        CP_COMMIT();
    }

#pragma unroll
    for (int m = 0; m < 2; m++) {
        const int row = i0 + wm * 32 + m * 16 + (lane >> 2);
        float* d0 = out + (size_t)row * DD;
        float* d1 = d0 + (size_t)8 * DD;
#pragma unroll
        for (int nt = 0; nt < 2; nt++) {
#pragma unroll
            for (int n8 = 0; n8 < 2; n8++) {
                const int col = j0 + wn * 32 + nt * 16 + n8 * 8 + 2 * (lane & 3);
                const float* c = &acc[(m * 2 + nt) * 8 + n8 * 4];
                const float b0 = bias[col];
                const float b1 = bias[col + 1];
                *reinterpret_cast<float2*>(d0 + col) = make_float2(c[0] + b0, c[1] + b1);
                *reinterpret_cast<float2*>(d1 + col) = make_float2(c[2] + b0, c[3] + b1);
            }
        }
    }
}

// ===========================================================================
extern "C" void kernel_launch(void* const* d_in, const int* in_sizes, int n_in,
                              void* d_out, int out_size)
{
    const float* Q    = (const float*)d_in[0];
    const float* K    = (const float*)d_in[1];
    const float* V    = (const float*)d_in[2];
    const float* Wo_w = (const float*)d_in[3];
    const float* Wo_b = (const float*)d_in[4];

    convert_all<<<1184, 256>>>(K, V, Wo_w);   // converts + meanv fused

    cudaFuncSetAttribute(attn_mma, cudaFuncAttributeMaxDynamicSharedMemorySize, SMEM_BYTES);
    dim3 agrid(SS / BM, HH, BB);          // (32, 16, 2)
    attn_mma<<<agrid, 256, SMEM_BYTES>>>(Q);

    dim3 pgrid(DD / 64, (BB * SS) / 128); // (16, 32)
    proj_mma2<<<pgrid, 256>>>(Wo_b, (float*)d_out);
}

// round 17
// speedup vs baseline: 1.2221x; 1.0766x over previous
#include <cuda_runtime.h>
#include <cuda_fp16.h>
#include <math.h>
#include <stdint.h>

// Problem constants
#define BB 2
#define SS 2048
#define DD 1024
#define HH 16
#define DQ 64

// Attention tiling
#define BM 64
#define BN 64

// ctx scratch (single fp16)
__device__ __half g_ctx_h[BB * SS * DD];
// W hi fp16
__device__ __half g_w_h[DD * DD];
// K hi; V hi (single fp16 each)
__device__ __half g_k_h[BB * SS * DD];
__device__ __half g_v_h[BB * SS * DD];

// ===========================================================================
// Helpers
// ===========================================================================
__device__ __forceinline__ uint32_t smem_u32(const void* p) {
    uint32_t a;
    asm("{ .reg .u64 t; cvta.to.shared.u64 t, %1; cvt.u32.u64 %0, t; }" : "=r"(a) : "l"(p));
    return a;
}
__device__ __forceinline__ uint32_t swz(uint32_t off) {
    return off ^ ((off >> 3) & 0x70);
}
__device__ __forceinline__ void ldsm4(uint32_t* r, uint32_t addr) {
    asm volatile("ldmatrix.sync.aligned.m8n8.x4.shared.b16 {%0,%1,%2,%3}, [%4];"
                 : "=r"(r[0]), "=r"(r[1]), "=r"(r[2]), "=r"(r[3]) : "r"(addr));
}
__device__ __forceinline__ void ldsm4t(uint32_t* r, uint32_t addr) {
    asm volatile("ldmatrix.sync.aligned.m8n8.x4.trans.shared.b16 {%0,%1,%2,%3}, [%4];"
                 : "=r"(r[0]), "=r"(r[1]), "=r"(r[2]), "=r"(r[3]) : "r"(addr));
}
__device__ __forceinline__ void mma16816(float* c, const uint32_t* a, uint32_t b0, uint32_t b1) {
    asm volatile("mma.sync.aligned.m16n8k16.row.col.f32.f16.f16.f32 "
                 "{%0,%1,%2,%3}, {%4,%5,%6,%7}, {%8,%9}, {%0,%1,%2,%3};"
                 : "+f"(c[0]), "+f"(c[1]), "+f"(c[2]), "+f"(c[3])
                 : "r"(a[0]), "r"(a[1]), "r"(a[2]), "r"(a[3]), "r"(b0), "r"(b1));
}
__device__ __forceinline__ uint2 pack4h(float4 v) {
    __half2 a = __floats2half2_rn(v.x, v.y);
    __half2 b = __floats2half2_rn(v.z, v.w);
    uint2 r;
    r.x = *reinterpret_cast<uint32_t*>(&a);
    r.y = *reinterpret_cast<uint32_t*>(&b);
    return r;
}
__device__ __forceinline__ uint32_t pack2h(float x, float y) {
    __half2 h = __floats2half2_rn(x, y);
    return *reinterpret_cast<uint32_t*>(&h);
}
__device__ __forceinline__ void cpa16(uint32_t d, const void* s) {
    asm volatile("cp.async.cg.shared.global [%0], [%1], 16;" :: "r"(d), "l"(s));
}
#define CP_COMMIT() asm volatile("cp.async.commit_group;" ::: "memory")
#define CP_WAIT0()  asm volatile("cp.async.wait_group 0;" ::: "memory")
#define CP_WAIT1()  asm volatile("cp.async.wait_group 1;" ::: "memory")

// exp2 constant: 0.125 (scale) * log2(e)
#define EXPC 0.1803368801111244f

// ===========================================================================
// Fused converter + row-0 fix:
//   blocks [0,512)     K -> fp16   (coalesced: 1 KB/instr loads)
//   blocks [512,1024)  V -> fp16
//   blocks [1024,1152) W -> fp16
//   blocks [1152,1184) meanv: ctx(q=0) = mean_s V, float4 lanes, 128 keys/thr
// ===========================================================================
extern "C" __global__ void __launch_bounds__(256)
convert_all(const float* __restrict__ K,
            const float* __restrict__ V,
            const float* __restrict__ W)
{
    __shared__ float4 red4[256];
    const int bid = blockIdx.x;
    const int tid = threadIdx.x;

    if (bid < 1152) {
        const float4* src;
        uint4* dst;
        int base;
        if (bid < 512) {
            src = reinterpret_cast<const float4*>(K);
            dst = reinterpret_cast<uint4*>(g_k_h);
            base = bid * 1024;
        } else if (bid < 1024) {
            src = reinterpret_cast<const float4*>(V);
            dst = reinterpret_cast<uint4*>(g_v_h);
            base = (bid - 512) * 1024;
        } else {
            src = reinterpret_cast<const float4*>(W);
            dst = reinterpret_cast<uint4*>(g_w_h);
            base = (bid - 1024) * 1024;
        }
        float4 a[4], b[4];
#pragma unroll
        for (int j = 0; j < 4; j++) {
            const int o = base + j * 256 + tid;
            a[j] = src[2 * o];
            b[j] = src[2 * o + 1];
        }
#pragma unroll
        for (int j = 0; j < 4; j++) {
            const int o = base + j * 256 + tid;
            uint2 pa = pack4h(a[j]), pb = pack4h(b[j]);
            dst[o] = make_uint4(pa.x, pa.y, pb.x, pb.y);
        }
    } else {
        // meanv: ctx row 0 = mean over 2048 keys of V (per b, h).
        // thread = (d4 in [0,16), sc in [0,16)); each sums 128 keys as float4.
        const int idx = bid - 1152;
        const int h = idx & 15;
        const int b = idx >> 4;
        const int d4 = tid & 15;
        const int sc = tid >> 4;
        const float4* src = reinterpret_cast<const float4*>(V + (size_t)b * SS * DD + h * DQ) + d4;
        float4 acc = make_float4(0.f, 0.f, 0.f, 0.f);
#pragma unroll 8
        for (int i = sc * 128; i < sc * 128 + 128; i++) {
            float4 v = src[(size_t)i * (DD / 4)];
            acc.x += v.x; acc.y += v.y; acc.z += v.z; acc.w += v.w;
        }
        red4[tid] = acc;
        __syncthreads();
        if (tid < 16) {
            float4 s = red4[tid];
#pragma unroll
            for (int j = 1; j < 16; j++) {
                float4 t = red4[j * 16 + tid];
                s.x += t.x; s.y += t.y; s.z += t.z; s.w += t.w;
            }
            const float inv = 1.0f / 2048.0f;
            uint2 p = pack4h(make_float4(s.x * inv, s.y * inv, s.z * inv, s.w * inv));
            *reinterpret_cast<uint2*>(&g_ctx_h[(size_t)b * SS * DD + h * DQ + d4 * 4]) = p;
        }
    }
}

// ===========================================================================
// Attention smem: Q hi (8 KB) + 2 stages x (KH, VH) (16 KB each) = 40 KB.
// Cross-warp reduce buffer reuses [0, ~18 KB) after the main loop.
// ===========================================================================
#define SM_QH   0
#define SM_STG  8192
#define STG_STR 16384
#define SMEM_BYTES 40960
#define RED_STR 35

// ===========================================================================
// Flash attention (R12-proven): fp16 HMMA, pipelined K/V, 8 warps
// (16 rows x 32 keys). QK 1-term (Q frags hoisted), PV 1-term.
// Row-0 store skipped (meanv owns it). Grid (32,16,2), 256 threads.
// ===========================================================================
extern "C" __global__ void __launch_bounds__(256, 2)
attn_mma(const float* __restrict__ Q)
{
    extern __shared__ char smc[];
    const uint32_t sb = smem_u32(smc);
    const int tid  = threadIdx.x;
    const int lane = tid & 31;
    const int wid  = tid >> 5;
    const int wr   = wid >> 1;    // row group 0..3
    const int wk   = wid & 1;     // key half 0..1

    const int bx = blockIdx.x;
    const int qt = (bx == 31) ? 0 : (31 - bx);
    const int h  = blockIdx.y;
    const int b  = blockIdx.z;
    const int q0 = qt * BM;

    const float* Qb  = Q + ((size_t)(b * SS + q0)) * DD + h * DQ;
    const size_t kvb = (size_t)b * SS * DD + h * DQ;

    const int nkt = qt + 1;

    auto prefetch = [&](int stage, int k0) {
        const uint32_t stg = sb + SM_STG + stage * STG_STR;
#pragma unroll
        for (int q = 0; q < 2; q++) {
            const int id = q * 256 + tid;     // 0..511
            const int r = id >> 3;
            const int g = id & 7;
            const uint32_t off = swz((uint32_t)(r * 128 + g * 16));
            const size_t srco = kvb + (size_t)(k0 + r) * DD + g * 8;
            cpa16(stg + off,        &g_k_h[srco]);
            cpa16(stg + 8192 + off, &g_v_h[srco]);
        }
    };

    prefetch(0, 0);
    CP_COMMIT();

    // ---- Load Q tile (hi only; overlaps stage-0 prefetch) ----
#pragma unroll
    for (int it = 0; it < 4; it++) {
        int idx = it * 256 + tid;
        int r = idx >> 4;
        int g = idx & 15;
        float4 q4 = *reinterpret_cast<const float4*>(Qb + (size_t)r * DD + g * 4);
        uint32_t off = swz((uint32_t)(r * 128 + g * 8));
        *reinterpret_cast<uint2*>(smc + SM_QH + off) = pack4h(q4);
    }
    __syncthreads();

    // ---- Hoist Q fragments (loop-invariant across k-tiles) ----
    uint32_t ah[4][4];
#pragma unroll
    for (int kc = 0; kc < 4; kc++) {
        uint32_t offA = swz((uint32_t)((wr * 16 + (lane & 15)) * 128 +
                                       (kc * 16 + (lane >> 4) * 8) * 2));
        ldsm4(ah[kc], sb + SM_QH + offA);
    }

    float Oa[32];
    float l0 = 0.0f, l1 = 0.0f;
#pragma unroll
    for (int i = 0; i < 32; i++) Oa[i] = 0.0f;

    const int qg0 = q0 + wr * 16 + (lane >> 2);
    const int qg1 = qg0 + 8;

    for (int kt = 0; kt < nkt; kt++) {
        const int k0 = kt * BN;

        if (kt + 1 < nkt) {
            prefetch((kt + 1) & 1, k0 + BN);
            CP_COMMIT();
            CP_WAIT1();
        } else {
            CP_WAIT0();
        }
        __syncthreads();

        const uint32_t stg = sb + SM_STG + (kt & 1) * STG_STR;

        // ---- S(16x32) = Qh Kh^T : 1-term ----
        float sc[16];
#pragma unroll
        for (int i = 0; i < 16; i++) sc[i] = 0.0f;

#pragma unroll
        for (int kc = 0; kc < 4; kc++) {
#pragma unroll
            for (int nt4 = 0; nt4 < 2; nt4++) {
                uint32_t offB = swz((uint32_t)((wk * 32 + nt4 * 16 + (lane & 7) + ((lane >> 4) << 3)) * 128 +
                                               (kc * 16 + ((lane >> 3) & 1) * 8) * 2));
                uint32_t bh[4];
                ldsm4(bh, stg + offB);
                mma16816(&sc[nt4 * 8],     ah[kc], bh[0], bh[1]);
                mma16816(&sc[nt4 * 8 + 4], ah[kc], bh[2], bh[3]);
            }
        }

        // ---- softmax (masked -> 0 exactly); single-fp16 P ----
        uint32_t pf[8];
#pragma unroll
        for (int nt = 0; nt < 4; nt++) {
            const int kg = k0 + wk * 32 + nt * 8 + 2 * (lane & 3);
            float p0 = (kg     >= qg0) ? 0.0f : exp2f(sc[nt * 4 + 0] * EXPC);
            float p1 = (kg + 1 >= qg0) ? 0.0f : exp2f(sc[nt * 4 + 1] * EXPC);
            float p2 = (kg     >= qg1) ? 0.0f : exp2f(sc[nt * 4 + 2] * EXPC);
            float p3 = (kg + 1 >= qg1) ? 0.0f : exp2f(sc[nt * 4 + 3] * EXPC);
            l0 += p0 + p1;
            l1 += p2 + p3;
            pf[nt * 2 + 0] = pack2h(p0, p1);
            pf[nt * 2 + 1] = pack2h(p2, p3);
        }

        // ---- O(partial over key-half) += P V : 1-term ----
#pragma unroll
        for (int c = 0; c < 2; c++) {
            const uint32_t* pa = &pf[c * 4];
#pragma unroll
            for (int d4 = 0; d4 < 4; d4++) {
                uint32_t offV = swz((uint32_t)((wk * 32 + c * 16 + (lane & 7) + ((lane >> 3) & 1) * 8) * 128 +
                                               (d4 * 16 + (lane >> 4) * 8) * 2));
                uint32_t bh[4];
                ldsm4t(bh, stg + 8192 + offV);
                mma16816(&Oa[d4 * 8],     pa, bh[0], bh[1]);
                mma16816(&Oa[d4 * 8 + 4], pa, bh[2], bh[3]);
            }
        }
        __syncthreads();
    }

    // ---- Cross-warp (key-half) reduction via smem ----
    float* sred = reinterpret_cast<float*>(smc);   // [4][32][RED_STR]
    float* slot = sred + (wr * 32 + lane) * RED_STR;
    if (wk == 1) {
#pragma unroll
        for (int i = 0; i < 32; i++) slot[i] = Oa[i];
        slot[32] = l0;
        slot[33] = l1;
    }
    __syncthreads();
    if (wk == 0) {
#pragma unroll
        for (int i = 0; i < 32; i++) Oa[i] += slot[i];
        l0 += slot[32];
        l1 += slot[33];

        l0 += __shfl_xor_sync(0xffffffffu, l0, 1);
        l0 += __shfl_xor_sync(0xffffffffu, l0, 2);
        l1 += __shfl_xor_sync(0xffffffffu, l1, 1);
        l1 += __shfl_xor_sync(0xffffffffu, l1, 2);
        const float inv0 = (l0 > 0.0f) ? 1.0f / l0 : 0.0f;
        const float inv1 = 1.0f / l1;

        const int row0 = q0 + wr * 16 + (lane >> 2);
        const size_t base0 = ((size_t)(b * SS + row0)) * DD + h * DQ;
        const size_t base1 = base0 + (size_t)8 * DD;
#pragma unroll
        for (int nt = 0; nt < 8; nt++) {
            const int col = nt * 8 + 2 * (lane & 3);
            if (row0 != 0) {   // row 0 owned by meanv (runs in convert_all)
                *reinterpret_cast<uint32_t*>(&g_ctx_h[base0 + col]) =
                    pack2h(Oa[nt * 4 + 0] * inv0, Oa[nt * 4 + 1] * inv0);
            }
            *reinterpret_cast<uint32_t*>(&g_ctx_h[base1 + col]) =
                pack2h(Oa[nt * 4 + 2] * inv1, Oa[nt * 4 + 3] * inv1);
        }
    }
}

// ===========================================================================
// Projection (unchanged R12): 1-term fp16 GEMM, CTA 128x64, BK=64, 256 thr.
// ===========================================================================
#define PNIT (DD / 64)

extern "C" __global__ void __launch_bounds__(256, 2)
proj_mma2(const float* __restrict__ bias,
          float* __restrict__ out)
{
    __shared__ __align__(16) char sA[2][16384];
    __shared__ __align__(16) char sB[2][8192];

    const int tid  = threadIdx.x;
    const int lane = tid & 31;
    const int wid  = tid >> 5;
    const int wm   = wid >> 1;
    const int wn   = wid & 1;
    const int j0   = blockIdx.x * 64;
    const int i0   = blockIdx.y * 128;

    const uint32_t sa0 = smem_u32(sA[0]);
    const uint32_t sa1 = smem_u32(sA[1]);
    const uint32_t sb0 = smem_u32(sB[0]);
    const uint32_t sb1 = smem_u32(sB[1]);

    float acc[32];
#pragma unroll
    for (int i = 0; i < 32; i++) acc[i] = 0.0f;

    auto issue = [&](int stage, int k0) {
        const uint32_t sa = stage ? sa1 : sa0;
        const uint32_t sbm = stage ? sb1 : sb0;
#pragma unroll
        for (int q = 0; q < 4; q++) {
            int id = q * 256 + tid;
            int r = id >> 3;
            int g = id & 7;
            cpa16(sa + swz((uint32_t)(r * 128 + g * 16)),
                  &g_ctx_h[(size_t)(i0 + r) * DD + k0 + g * 8]);
        }
#pragma unroll
        for (int q = 0; q < 2; q++) {
            int id = q * 256 + tid;
            int r = id >> 3;
            int g = id & 7;
            cpa16(sbm + swz((uint32_t)(r * 128 + g * 16)),
                  &g_w_h[(size_t)(j0 + r) * DD + k0 + g * 8]);
        }
    };

    issue(0, 0);  CP_COMMIT();
    issue(1, 64); CP_COMMIT();

    for (int it = 0; it < PNIT; it++) {
        CP_WAIT1();
        __syncthreads();
        const uint32_t sa = (it & 1) ? sa1 : sa0;
        const uint32_t sbm = (it & 1) ? sb1 : sb0;

#pragma unroll
        for (int kc = 0; kc < 4; kc++) {
            uint32_t ah[2][4];
#pragma unroll
            for (int m = 0; m < 2; m++) {
                const uint32_t row = wm * 32 + m * 16 + (lane & 15);
                const uint32_t colb = (kc * 16 + (lane >> 4) * 8) * 2;
                ldsm4(ah[m], sa + swz(row * 128 + colb));
            }
            uint32_t bh[2][4];
#pragma unroll
            for (int nt = 0; nt < 2; nt++) {
                const uint32_t rowb = wn * 32 + nt * 16 + (lane & 7) + ((lane >> 4) << 3);
                const uint32_t colb = (kc * 16 + ((lane >> 3) & 1) * 8) * 2;
                ldsm4(bh[nt], sbm + swz(rowb * 128 + colb));
            }
#pragma unroll
            for (int m = 0; m < 2; m++)
#pragma unroll
                for (int nt = 0; nt < 2; nt++) {
                    float* c0 = &acc[(m * 2 + nt) * 8];
                    float* c1 = c0 + 4;
                    mma16816(c0, ah[m], bh[nt][0], bh[nt][1]);
                    mma16816(c1, ah[m], bh[nt][2], bh[nt][3]);
                }
        }

        __syncthreads();
        if (it + 2 < PNIT) {
            issue(it & 1, (it + 2) * 64);
        }
        CP_COMMIT();
    }

#pragma unroll
    for (int m = 0; m < 2; m++) {
        const int row = i0 + wm * 32 + m * 16 + (lane >> 2);
        float* d0 = out + (size_t)row * DD;
        float* d1 = d0 + (size_t)8 * DD;
#pragma unroll
        for (int nt = 0; nt < 2; nt++) {
#pragma unroll
            for (int n8 = 0; n8 < 2; n8++) {
                const int col = j0 + wn * 32 + nt * 16 + n8 * 8 + 2 * (lane & 3);
                const float* c = &acc[(m * 2 + nt) * 8 + n8 * 4];
                const float b0 = bias[col];
                const float b1 = bias[col + 1];
                *reinterpret_cast<float2*>(d0 + col) = make_float2(c[0] + b0, c[1] + b1);
                *reinterpret_cast<float2*>(d1 + col) = make_float2(c[2] + b0, c[3] + b1);
            }
        }
    }
}

// ===========================================================================
extern "C" void kernel_launch(void* const* d_in, const int* in_sizes, int n_in,
                              void* d_out, int out_size)
{
    const float* Q    = (const float*)d_in[0];
    const float* K    = (const float*)d_in[1];
    const float* V    = (const float*)d_in[2];
    const float* Wo_w = (const float*)d_in[3];
    const float* Wo_b = (const float*)d_in[4];

    convert_all<<<1184, 256>>>(K, V, Wo_w);   // converts + meanv fused

    cudaFuncSetAttribute(attn_mma, cudaFuncAttributeMaxDynamicSharedMemorySize, SMEM_BYTES);
    dim3 agrid(SS / BM, HH, BB);          // (32, 16, 2)
    attn_mma<<<agrid, 256, SMEM_BYTES>>>(Q);

    dim3 pgrid(DD / 64, (BB * SS) / 128); // (16, 32)
    proj_mma2<<<pgrid, 256>>>(Wo_b, (float*)d_out);
}